// round 10
// baseline (speedup 1.0000x reference)
#include <cuda_runtime.h>

// Problem constants
#define B_   1024
#define I_   256
#define J_   256
#define K_   64

// Tiling
#define TB   128           // b per CTA (R10: doubled for L1 reuse)
#define TJ   64            // j per CTA
#define ISPL 8             // i-splits (partial sums)
#define IPC  (I_ / ISPL)   // 32 iterations per CTA
#define NTHR 512           // 16 warps, 8 b per warp (two half-groups of 4)
#define BPW  8
#define NBT  (B_ / TB)     // 8
#define NJT  (J_ / TJ)     // 4

// Static device scratch (no allocations allowed)
__device__ float        g_Yt[I_ * K_ * J_];             // Y transposed [i][k][j], 16.8 MB
__device__ int4         g_prep[I_ * B_];                // [i][b]: {w0,w1,absOff0B,absOff1B}
__device__ float4       g_part4[ISPL * B_ * J_ / 4];    // i-split partials (8 MB)
__device__ unsigned int g_cnt[NBT * NJT];               // last-block counters (self-resetting)

#define NT_BLOCKS (I_ * (J_ / 32) * (K_ / 32))          // 4096 transpose blocks
#define NP_BLOCKS ((B_ / 64) * (I_ / 64))               // 64 prep blocks

// ---------------------------------------------------------------------------
// pre_kernel: fused Y-transpose + interval/weight prep (disjoint block ranges
// run concurrently). Transpose: 32x32 fp32 tiles via smem, coalesced both
// sides, conflict-free smem (stride 33). Prep: smem-transposed x reads so both
// the x loads and the g_prep stores are coalesced. Offsets are now ABSOLUTE
// byte offsets into g_Yt: off0 = ((i*K + k) * J) * 4.
// ---------------------------------------------------------------------------
__global__ void __launch_bounds__(256) pre_kernel(const float* __restrict__ x,
                                                  const float* __restrict__ Xg,
                                                  const float* __restrict__ Y) {
    const int bid = blockIdx.x;
    const int tid = threadIdx.x;

    if (bid < NT_BLOCKS) {
        // ---- transpose Y[i][j][k] -> Yt[i][k][j], one 32x32 tile ----
        __shared__ float s[32][33];
        const int i    = bid >> 4;
        const int rest = bid & 15;
        const int jb   = (rest >> 1) * 32;
        const int kb   = (rest & 1) * 32;
        const float* src = Y + (size_t)i * (J_ * K_);

        int jj = tid >> 3, kq = (tid & 7) << 2;
        float4 v = *(const float4*)(src + (size_t)(jb + jj) * K_ + kb + kq);
        s[jj][kq + 0] = v.x; s[jj][kq + 1] = v.y;
        s[jj][kq + 2] = v.z; s[jj][kq + 3] = v.w;
        __syncthreads();

        int k = tid >> 3, jq = (tid & 7) << 2;
        float4 o = make_float4(s[jq + 0][k], s[jq + 1][k], s[jq + 2][k], s[jq + 3][k]);
        *(float4*)(g_Yt + (size_t)i * (K_ * J_) + (size_t)(kb + k) * J_ + jb + jq) = o;
    } else {
        // ---- prep: 64 b x 64 i tile ----
        __shared__ float xs[64][65];
        __shared__ float Xs[K_];
        const int p  = bid - NT_BLOCKS;
        const int b0 = (p & 15) * 64;
        const int i0 = (p >> 4) * 64;
        if (tid < K_) Xs[tid] = Xg[tid];

        // Stage the FULL 64x64 x-tile: 1024 float4s, 256 threads x 4.
        {
            int bb  = tid >> 2;                         // 0..63 (b row)
            int iq0 = (tid & 3) << 2;                   // 0,4,8,12
            #pragma unroll
            for (int r = 0; r < 4; ++r) {
                int iq = iq0 + r * 16;                  // covers 0..63
                float4 v = *(const float4*)(x + (size_t)(b0 + bb) * I_ + i0 + iq);
                xs[bb][iq + 0] = v.x; xs[bb][iq + 1] = v.y;
                xs[bb][iq + 2] = v.z; xs[bb][iq + 3] = v.w;
            }
        }
        __syncthreads();

        const int b  = tid & 63;
        const int ig = tid >> 6;
        const float X0   = Xs[0];
        const float hinv = (float)(K_ - 1) / (Xs[K_ - 1] - X0);
        #pragma unroll 4
        for (int q = 0; q < 16; ++q) {
            int   i  = ig * 16 + q;
            float xv = xs[b][i];                        // conflict-free (stride 65)
            int k = (int)floorf((xv - X0) * hinv);
            k = min(max(k, 0), K_ - 2);
            // exact fixup vs true grid (matches searchsorted side="right",
            // idx clipped to [1,K-1])
            while (k > 0 && xv < Xs[k]) --k;
            while (k < K_ - 2 && xv >= Xs[k + 1]) ++k;
            float x0 = Xs[k], x1 = Xs[k + 1];
            float tt = (xv - x0) / (x1 - x0);           // extrapolates at edges
            int off0 = ((i0 + i) * K_ + k) * (J_ * 4);  // ABSOLUTE byte offset in g_Yt
            g_prep[(size_t)(i0 + i) * B_ + b0 + b] =
                make_int4(__float_as_int(1.0f - tt), __float_as_int(tt),
                          off0, off0 + J_ * 4);
        }
    }
}

// ---------------------------------------------------------------------------
// main_kernel: grid (8,4,8) = 256 CTAs, 512 threads, 16 warps x 8 b
// (two sequential half-groups of 4 to bound the live register set).
// Prep slab (IPC x TB int4 = 64KB) staged to smem once; mainloop has no
// prep LDGs, absolute y offsets (loop-invariant base pointer).
// TB=128 doubles per-i-tile L1 reuse vs R9 (the 60.5%-l1tex limiter was
// L2-latency on the ~1/3 of y-loads missing L1).
// Last CTA per (bt,jt) reduces the ISPL=8 partials (deterministic order).
// ---------------------------------------------------------------------------
__global__ void __launch_bounds__(NTHR, 2)
main_kernel(float* __restrict__ outp) {
    __shared__ int4 s_prep[IPC][TB];           // 64 KB
    __shared__ unsigned int s_last;

    const int bt = blockIdx.x;                 // 0..7
    const int jt = blockIdx.y;                 // 0..3
    const int it = blockIdx.z;                 // 0..7
    const int i0 = it * IPC;
    const int j0 = jt * TJ;
    const int b0 = bt * TB;

    const int w    = threadIdx.x >> 5;         // 0..15
    const int lane = threadIdx.x & 31;
    const int wb   = w * BPW;                  // warp's first local b

    // ---- stage prep slab: 4096 int4s, 512 threads x 8 coalesced rounds ----
    {
        const int4* gp = g_prep + (size_t)i0 * B_ + b0;
        #pragma unroll
        for (int r = 0; r < (IPC * TB) / NTHR; ++r) {
            int flat = threadIdx.x + r * NTHR;
            int ii = flat >> 7;                // / TB
            int b  = flat & (TB - 1);
            s_prep[ii][b] = gp[(size_t)ii * B_ + b];
        }
    }
    __syncthreads();

    unsigned long long acc[BPW];
    #pragma unroll
    for (int q = 0; q < BPW; ++q) acc[q] = 0ULL;   // {0.f, 0.f}

    const char* ybase = (const char*)g_Yt + (size_t)(j0 + 2 * lane) * 4;

    for (int ii = 0; ii < IPC; ++ii) {
        #pragma unroll
        for (int h = 0; h < 2; ++h) {          // two half-groups of 4 b's
            int4 p[4];
            #pragma unroll
            for (int bb = 0; bb < 4; ++bb) p[bb] = s_prep[ii][wb + h * 4 + bb];
            #pragma unroll
            for (int bb = 0; bb < 4; ++bb) {
                unsigned long long y0 = *(const unsigned long long*)(ybase + p[bb].z);
                unsigned long long y1 = *(const unsigned long long*)(ybase + p[bb].w);
                unsigned long long W0, W1;
                asm("mov.b64 %0, {%1, %1};" : "=l"(W0) : "r"(p[bb].x));
                asm("mov.b64 %0, {%1, %1};" : "=l"(W1) : "r"(p[bb].y));
                asm("fma.rn.f32x2 %0, %1, %2, %0;" : "+l"(acc[h * 4 + bb]) : "l"(W0), "l"(y0));
                asm("fma.rn.f32x2 %0, %1, %2, %0;" : "+l"(acc[h * 4 + bb]) : "l"(W1), "l"(y1));
            }
        }
    }

    // write partial sums (deterministic, per-it slice)
    float* part = (float*)g_part4 + (size_t)it * (B_ * J_);
    const int bw = b0 + wb;
    #pragma unroll
    for (int bb = 0; bb < BPW; ++bb) {
        *(unsigned long long*)(part + (size_t)(bw + bb) * J_ + j0 + 2 * lane) = acc[bb];
    }

    // ---- fused last-block reduction over the ISPL partials ----
    __threadfence();                           // publish partials (release)
    if (threadIdx.x == 0) {
        unsigned int old = atomicAdd(&g_cnt[bt * NJT + jt], 1u);
        s_last = (old == ISPL - 1) ? 1u : 0u;
    }
    __syncthreads();
    if (s_last) {
        __threadfence();                       // acquire other CTAs' partials
        if (threadIdx.x == 0) g_cnt[bt * NJT + jt] = 0;   // self-reset for replay
        const int stride = B_ * J_ / 4;
        for (int t = threadIdx.x; t < TB * TJ / 4; t += NTHR) {
            int row = t >> 4;                  // 0..127  (TJ/4 = 16)
            int c4  = t & 15;
            size_t idx = (((size_t)(b0 + row) * J_ + j0) >> 2) + c4;
            float4 p0 = g_part4[idx];
            float4 p1 = g_part4[idx + stride];
            float4 p2 = g_part4[idx + 2 * stride];
            float4 p3 = g_part4[idx + 3 * stride];
            float4 p4 = g_part4[idx + 4 * stride];
            float4 p5 = g_part4[idx + 5 * stride];
            float4 p6 = g_part4[idx + 6 * stride];
            float4 p7 = g_part4[idx + 7 * stride];
            float4 r;
            r.x = ((p0.x + p1.x) + (p2.x + p3.x)) + ((p4.x + p5.x) + (p6.x + p7.x));
            r.y = ((p0.y + p1.y) + (p2.y + p3.y)) + ((p4.y + p5.y) + (p6.y + p7.y));
            r.z = ((p0.z + p1.z) + (p2.z + p3.z)) + ((p4.z + p5.z) + (p6.z + p7.z));
            r.w = ((p0.w + p1.w) + (p2.w + p3.w)) + ((p4.w + p5.w) + (p6.w + p7.w));
            ((float4*)outp)[idx] = r;
        }
    }
}

// ---------------------------------------------------------------------------
extern "C" void kernel_launch(void* const* d_in, const int* in_sizes, int n_in,
                              void* d_out, int out_size) {
    const float* x  = (const float*)d_in[0];   // [B, I]
    const float* Xg = (const float*)d_in[1];   // [K]
    const float* Y  = (const float*)d_in[2];   // [I, J, K]
    float* out = (float*)d_out;                // [B, J]

    pre_kernel<<<NT_BLOCKS + NP_BLOCKS, 256>>>(x, Xg, Y);
    main_kernel<<<dim3(NBT, NJT, ISPL), NTHR>>>(out);
}

// round 11
// speedup vs baseline: 1.1550x; 1.1550x over previous
#include <cuda_runtime.h>

// Problem constants
#define B_   1024
#define I_   256
#define J_   256
#define K_   64

// Tiling
#define TB   64            // b per CTA (R10's 128 regressed -> revert)
#define TJ   128           // j per CTA (R11: 4 floats per lane, LDG.128 rows)
#define ISPL 8             // i-splits (keeps grid at 256 CTAs)
#define IPC  (I_ / ISPL)   // 32 iterations per CTA
#define NTHR 512           // 16 warps, 4 b per warp
#define BPW  4
#define NBT  (B_ / TB)     // 16
#define NJT  (J_ / TJ)     // 2

// Static device scratch (no allocations allowed)
__device__ float        g_Yt[I_ * K_ * J_];             // Y transposed [i][k][j], 16.8 MB
__device__ int4         g_prep[I_ * B_];                // [i][b]: {w0,w1,absOff0B,absOff1B}
__device__ float4       g_part4[ISPL * B_ * J_ / 4];    // i-split partials (8 MB)
__device__ unsigned int g_cnt[NBT * NJT];               // last-block counters (self-resetting)

#define NT_BLOCKS (I_ * (J_ / 32) * (K_ / 32))          // 4096 transpose blocks
#define NP_BLOCKS ((B_ / 64) * (I_ / 64))               // 64 prep blocks

// ---------------------------------------------------------------------------
// pre_kernel: fused Y-transpose + interval/weight prep (disjoint block ranges
// run concurrently). Transpose: 32x32 fp32 tiles via smem, coalesced both
// sides, conflict-free smem (stride 33). Prep: smem-transposed x reads so both
// the x loads and the g_prep stores are coalesced. Offsets are ABSOLUTE byte
// offsets into g_Yt: off0 = ((i*K + k) * J) * 4.
// ---------------------------------------------------------------------------
__global__ void __launch_bounds__(256) pre_kernel(const float* __restrict__ x,
                                                  const float* __restrict__ Xg,
                                                  const float* __restrict__ Y) {
    const int bid = blockIdx.x;
    const int tid = threadIdx.x;

    if (bid < NT_BLOCKS) {
        // ---- transpose Y[i][j][k] -> Yt[i][k][j], one 32x32 tile ----
        __shared__ float s[32][33];
        const int i    = bid >> 4;
        const int rest = bid & 15;
        const int jb   = (rest >> 1) * 32;
        const int kb   = (rest & 1) * 32;
        const float* src = Y + (size_t)i * (J_ * K_);

        int jj = tid >> 3, kq = (tid & 7) << 2;
        float4 v = *(const float4*)(src + (size_t)(jb + jj) * K_ + kb + kq);
        s[jj][kq + 0] = v.x; s[jj][kq + 1] = v.y;
        s[jj][kq + 2] = v.z; s[jj][kq + 3] = v.w;
        __syncthreads();

        int k = tid >> 3, jq = (tid & 7) << 2;
        float4 o = make_float4(s[jq + 0][k], s[jq + 1][k], s[jq + 2][k], s[jq + 3][k]);
        *(float4*)(g_Yt + (size_t)i * (K_ * J_) + (size_t)(kb + k) * J_ + jb + jq) = o;
    } else {
        // ---- prep: 64 b x 64 i tile ----
        __shared__ float xs[64][65];
        __shared__ float Xs[K_];
        const int p  = bid - NT_BLOCKS;
        const int b0 = (p & 15) * 64;
        const int i0 = (p >> 4) * 64;
        if (tid < K_) Xs[tid] = Xg[tid];

        // Stage the FULL 64x64 x-tile: 1024 float4s, 256 threads x 4.
        {
            int bb  = tid >> 2;                         // 0..63 (b row)
            int iq0 = (tid & 3) << 2;                   // 0,4,8,12
            #pragma unroll
            for (int r = 0; r < 4; ++r) {
                int iq = iq0 + r * 16;                  // covers 0..63
                float4 v = *(const float4*)(x + (size_t)(b0 + bb) * I_ + i0 + iq);
                xs[bb][iq + 0] = v.x; xs[bb][iq + 1] = v.y;
                xs[bb][iq + 2] = v.z; xs[bb][iq + 3] = v.w;
            }
        }
        __syncthreads();

        const int b  = tid & 63;
        const int ig = tid >> 6;
        const float X0   = Xs[0];
        const float hinv = (float)(K_ - 1) / (Xs[K_ - 1] - X0);
        #pragma unroll 4
        for (int q = 0; q < 16; ++q) {
            int   i  = ig * 16 + q;
            float xv = xs[b][i];                        // conflict-free (stride 65)
            int k = (int)floorf((xv - X0) * hinv);
            k = min(max(k, 0), K_ - 2);
            // exact fixup vs true grid (matches searchsorted side="right",
            // idx clipped to [1,K-1])
            while (k > 0 && xv < Xs[k]) --k;
            while (k < K_ - 2 && xv >= Xs[k + 1]) ++k;
            float x0 = Xs[k], x1 = Xs[k + 1];
            float tt = (xv - x0) / (x1 - x0);           // extrapolates at edges
            int off0 = ((i0 + i) * K_ + k) * (J_ * 4);  // ABSOLUTE byte offset in g_Yt
            g_prep[(size_t)(i0 + i) * B_ + b0 + b] =
                make_int4(__float_as_int(1.0f - tt), __float_as_int(tt),
                          off0, off0 + J_ * 4);
        }
    }
}

// ---------------------------------------------------------------------------
// main_kernel: grid (16,2,8) = 256 CTAs, 512 threads, 16 warps x 4 b.
// R11: TJ=128 with 4 floats/lane -> each y row fetch is ONE LDG.128 (512B
// per warp) instead of two LDG.64 iterations. Per unit of work: 52 instrs
// vs R9's 84 (issue-bound limiter per R10 post-mortem). Prep slab (32KB)
// staged to smem once; no prep LDGs in the mainloop; absolute y offsets.
// Last CTA per (bt,jt) reduces the ISPL=8 partials (deterministic order).
// ---------------------------------------------------------------------------
__global__ void __launch_bounds__(NTHR, 2)
main_kernel(float* __restrict__ outp) {
    __shared__ int4 s_prep[IPC][TB];           // 32 KB
    __shared__ unsigned int s_last;

    const int bt = blockIdx.x;                 // 0..15
    const int jt = blockIdx.y;                 // 0..1
    const int it = blockIdx.z;                 // 0..7
    const int i0 = it * IPC;
    const int j0 = jt * TJ;
    const int b0 = bt * TB;

    const int w    = threadIdx.x >> 5;         // 0..15
    const int lane = threadIdx.x & 31;
    const int wb   = w * BPW;                  // warp's first local b

    // ---- stage prep slab: 2048 int4s, 512 threads x 4 coalesced rounds ----
    {
        const int4* gp = g_prep + (size_t)i0 * B_ + b0;
        #pragma unroll
        for (int r = 0; r < (IPC * TB) / NTHR; ++r) {
            int flat = threadIdx.x + r * NTHR;
            int ii = flat >> 6;                // / TB
            int b  = flat & (TB - 1);
            s_prep[ii][b] = gp[(size_t)ii * B_ + b];
        }
    }
    __syncthreads();

    // acc[bb] = 4 floats (2 packed f32x2) per b
    unsigned long long accA[BPW], accB[BPW];
    #pragma unroll
    for (int q = 0; q < BPW; ++q) { accA[q] = 0ULL; accB[q] = 0ULL; }

    const char* ybase = (const char*)g_Yt + (size_t)(j0 + 4 * lane) * 4;

    for (int ii = 0; ii < IPC; ++ii) {
        int4 p[BPW];
        #pragma unroll
        for (int bb = 0; bb < BPW; ++bb) p[bb] = s_prep[ii][wb + bb];   // LDS.128 broadcast
        #pragma unroll
        for (int bb = 0; bb < BPW; ++bb) {
            ulonglong2 y0 = *(const ulonglong2*)(ybase + p[bb].z);      // LDG.128
            ulonglong2 y1 = *(const ulonglong2*)(ybase + p[bb].w);      // LDG.128
            unsigned long long W0, W1;
            asm("mov.b64 %0, {%1, %1};" : "=l"(W0) : "r"(p[bb].x));
            asm("mov.b64 %0, {%1, %1};" : "=l"(W1) : "r"(p[bb].y));
            asm("fma.rn.f32x2 %0, %1, %2, %0;" : "+l"(accA[bb]) : "l"(W0), "l"(y0.x));
            asm("fma.rn.f32x2 %0, %1, %2, %0;" : "+l"(accB[bb]) : "l"(W0), "l"(y0.y));
            asm("fma.rn.f32x2 %0, %1, %2, %0;" : "+l"(accA[bb]) : "l"(W1), "l"(y1.x));
            asm("fma.rn.f32x2 %0, %1, %2, %0;" : "+l"(accB[bb]) : "l"(W1), "l"(y1.y));
        }
    }

    // write partial sums (deterministic, per-it slice), STG.128
    float* part = (float*)g_part4 + (size_t)it * (B_ * J_);
    const int bw = b0 + wb;
    #pragma unroll
    for (int bb = 0; bb < BPW; ++bb) {
        ulonglong2 v; v.x = accA[bb]; v.y = accB[bb];
        *(ulonglong2*)(part + (size_t)(bw + bb) * J_ + j0 + 4 * lane) = v;
    }

    // ---- fused last-block reduction over the ISPL partials ----
    __threadfence();                           // publish partials (release)
    if (threadIdx.x == 0) {
        unsigned int old = atomicAdd(&g_cnt[bt * NJT + jt], 1u);
        s_last = (old == ISPL - 1) ? 1u : 0u;
    }
    __syncthreads();
    if (s_last) {
        __threadfence();                       // acquire other CTAs' partials
        if (threadIdx.x == 0) g_cnt[bt * NJT + jt] = 0;   // self-reset for replay
        const int stride = B_ * J_ / 4;
        for (int t = threadIdx.x; t < TB * TJ / 4; t += NTHR) {
            int row = t >> 5;                  // 0..63   (TJ/4 = 32)
            int c4  = t & 31;
            size_t idx = (((size_t)(b0 + row) * J_ + j0) >> 2) + c4;
            float4 p0 = g_part4[idx];
            float4 p1 = g_part4[idx + stride];
            float4 p2 = g_part4[idx + 2 * stride];
            float4 p3 = g_part4[idx + 3 * stride];
            float4 p4 = g_part4[idx + 4 * stride];
            float4 p5 = g_part4[idx + 5 * stride];
            float4 p6 = g_part4[idx + 6 * stride];
            float4 p7 = g_part4[idx + 7 * stride];
            float4 r;
            r.x = ((p0.x + p1.x) + (p2.x + p3.x)) + ((p4.x + p5.x) + (p6.x + p7.x));
            r.y = ((p0.y + p1.y) + (p2.y + p3.y)) + ((p4.y + p5.y) + (p6.y + p7.y));
            r.z = ((p0.z + p1.z) + (p2.z + p3.z)) + ((p4.z + p5.z) + (p6.z + p7.z));
            r.w = ((p0.w + p1.w) + (p2.w + p3.w)) + ((p4.w + p5.w) + (p6.w + p7.w));
            ((float4*)outp)[idx] = r;
        }
    }
}

// ---------------------------------------------------------------------------
extern "C" void kernel_launch(void* const* d_in, const int* in_sizes, int n_in,
                              void* d_out, int out_size) {
    const float* x  = (const float*)d_in[0];   // [B, I]
    const float* Xg = (const float*)d_in[1];   // [K]
    const float* Y  = (const float*)d_in[2];   // [I, J, K]
    float* out = (float*)d_out;                // [B, J]

    pre_kernel<<<NT_BLOCKS + NP_BLOCKS, 256>>>(x, Xg, Y);
    main_kernel<<<dim3(NBT, NJT, ISPL), NTHR>>>(out);
}